// round 14
// baseline (speedup 1.0000x reference)
#include <cuda_runtime.h>

// Loss: per element, 9 shifted abs-diffs (3x3 target neighborhood, OOB=0),
// smooth-min via logsumexp(k=32), out = 0.5*(mean(center)+mean(smin)).
//
// R14: kernel is on the MUFU roofline (10 XU ops/elem -> 44.3k cyc floor,
// measured 59k). (a) lg2 -> integer-exponent + sqrt2-folded deg-4 Taylor on
// fma/alu pipes (NO I2F - that's also XU), MUFU 10->9/elem. (b) pairwise
// tree-sum of the 9 exp terms (dep depth 8 FADD -> 4).

constexpr int BATCH = 64;
constexpr int TLEN  = 2048;   // power of 2 -> t via mask
constexpr int DIM   = 80;
constexpr int D4    = DIM / 4;                       // 20 float4 per row
constexpr int N4    = BATCH * TLEN * D4;             // 2,621,440 float4
constexpr float INV_NELEM = 1.0f / (float)((long long)BATCH * TLEN * DIM);

constexpr int THREADS = 256;
constexpr int GRID    = 740;                         // 148 SMs x 5 resident CTAs
constexpr int STRIDE  = GRID * THREADS;              // grid-stride

__device__ float2 g_partials[GRID];                  // static scratch (no alloc)
__device__ unsigned int g_ticket;                    // zero-init; last block resets

__device__ __forceinline__ float fast_ex2(float x) {
    float y; asm("ex2.approx.ftz.f32 %0, %1;" : "=f"(y) : "f"(x)); return y;
}

// log2(s) for s in [1, 9] via exponent extraction + Taylor on the sqrt2-folded
// mantissa. All fma/alu-pipe ops; exponent int->float via 0x4B000000 magic
// (OR + FADD), deliberately avoiding I2F (XU pipe). Max err ~2.8e-3 ->
// contributes <= 7e-5 to sm through the *IKE=0.0217 scale. S>=1 always.
__device__ __forceinline__ float lg2_poly(float s) {
    int   i    = __float_as_int(s);
    float ef   = __int_as_float(0x4B000000 | (i >> 23)) - 8388735.0f; // 2^23 + 127
    float mant = __int_as_float((i & 0x007FFFFF) | 0x3F800000);       // [1,2)
    if (mant > 1.41421356f) { mant *= 0.5f; ef += 1.0f; }             // predicated
    float t = mant - 1.0f;                                            // [-0.293, 0.414)
    float p = fmaf(t, -0.25f, 0.33333333f);
    p = fmaf(t, p, -0.5f);
    p = fmaf(t, p, 1.0f);                        // 1 - t/2 + t^2/3 - t^3/4
    return fmaf(t * 1.44269504f, p, ef);         // e + log2e * t * p
}

__global__ __launch_bounds__(THREADS, 5)
void jitter_main(const float* __restrict__ inp, const float* __restrict__ tgt,
                 float* __restrict__ out) {
    const float4* __restrict__ in4  = reinterpret_cast<const float4*>(inp);
    const float4* __restrict__ tg4  = reinterpret_cast<const float4*>(tgt);

    const float KE   = 46.16624131f;   // 32 * log2(e)
    const float IKE  = 0.02166085f;    // ln(2) / 32

    float accC = 0.f, accS = 0.f;

    #pragma unroll 2
    for (int i4 = blockIdx.x * THREADS + threadIdx.x; i4 < N4; i4 += STRIDE) {
        int row = i4 / D4;                 // global row = b*TLEN + t
        int d4  = i4 - row * D4;           // float4 index within row
        int t   = row & (TLEN - 1);

        float4 xi = in4[i4];

        // target neighborhood: 3 rows x 6 dims [d0-1 .. d0+4], zeros at boundaries
        float nm[6], nc[6], np6[6];
        {
            // center row (always valid)
            float4 c = tg4[row * D4 + d4];
            nc[1] = c.x; nc[2] = c.y; nc[3] = c.z; nc[4] = c.w;
            nc[0] = (d4 > 0)      ? tgt[row * DIM + d4 * 4 - 1] : 0.f;
            nc[5] = (d4 < D4 - 1) ? tgt[row * DIM + d4 * 4 + 4] : 0.f;
        }
        if (t > 0) {
            int r = row - 1;
            float4 c = tg4[r * D4 + d4];
            nm[1] = c.x; nm[2] = c.y; nm[3] = c.z; nm[4] = c.w;
            nm[0] = (d4 > 0)      ? tgt[r * DIM + d4 * 4 - 1] : 0.f;
            nm[5] = (d4 < D4 - 1) ? tgt[r * DIM + d4 * 4 + 4] : 0.f;
        } else {
            #pragma unroll
            for (int i = 0; i < 6; i++) nm[i] = 0.f;
        }
        if (t < TLEN - 1) {
            int r = row + 1;
            float4 c = tg4[r * D4 + d4];
            np6[1] = c.x; np6[2] = c.y; np6[3] = c.z; np6[4] = c.w;
            np6[0] = (d4 > 0)      ? tgt[r * DIM + d4 * 4 - 1] : 0.f;
            np6[5] = (d4 < D4 - 1) ? tgt[r * DIM + d4 * 4 + 4] : 0.f;
        } else {
            #pragma unroll
            for (int i = 0; i < 6; i++) np6[i] = 0.f;
        }

        float xv[4] = {xi.x, xi.y, xi.z, xi.w};

        #pragma unroll
        for (int j = 0; j < 4; j++) {
            float x  = xv[j];
            // 9 shifted abs-diffs: diff(dt,dd) = |x - tgt[t+dt][d+dd]|
            float d0 = fabsf(x - nc [j + 1]);   // ( 0, 0)  center
            float d1 = fabsf(x - np6[j + 1]);   // (+1, 0)
            float d2 = fabsf(x - nm [j + 1]);   // (-1, 0)
            float d3 = fabsf(x - nc [j + 2]);   // ( 0,+1)
            float d4v= fabsf(x - nc [j    ]);   // ( 0,-1)
            float d5 = fabsf(x - np6[j + 2]);   // (+1,+1)
            float d6 = fabsf(x - nm [j    ]);   // (-1,-1)
            float d7 = fabsf(x - np6[j    ]);   // (+1,-1)
            float d8 = fabsf(x - nm [j + 2]);   // (-1,+1)

            float mn = fminf(fminf(fminf(d0, d1), fminf(d2, d3)),
                             fminf(fminf(fminf(d4v, d5), fminf(d6, d7)), d8));

            // logsumexp: arg_i = fma(d_i, -KE, mn*KE), one FFMA each.
            float mK = mn * KE;
            float e0 = fast_ex2(fmaf(d0 , -KE, mK));
            float e1 = fast_ex2(fmaf(d1 , -KE, mK));
            float e2 = fast_ex2(fmaf(d2 , -KE, mK));
            float e3 = fast_ex2(fmaf(d3 , -KE, mK));
            float e4 = fast_ex2(fmaf(d4v, -KE, mK));
            float e5 = fast_ex2(fmaf(d5 , -KE, mK));
            float e6 = fast_ex2(fmaf(d6 , -KE, mK));
            float e7 = fast_ex2(fmaf(d7 , -KE, mK));
            float e8 = fast_ex2(fmaf(d8 , -KE, mK));

            // pairwise tree: dep depth 4 instead of 8
            float S = (((e0 + e1) + (e2 + e3)) + ((e4 + e5) + (e6 + e7))) + e8;

            float sm = fmaf(lg2_poly(S), -IKE, mn);

            accC += d0;
            accS += sm;
        }
    }

    // warp reduce
    #pragma unroll
    for (int o = 16; o; o >>= 1) {
        accC += __shfl_xor_sync(0xFFFFFFFFu, accC, o);
        accS += __shfl_xor_sync(0xFFFFFFFFu, accS, o);
    }

    __shared__ float sC[8], sS[8];
    __shared__ bool  sLast;
    int lane = threadIdx.x & 31;
    int wid  = threadIdx.x >> 5;
    if (lane == 0) { sC[wid] = accC; sS[wid] = accS; }
    __syncthreads();

    if (threadIdx.x == 0) {
        float c = 0.f, s = 0.f;
        #pragma unroll
        for (int i = 0; i < 8; i++) { c += sC[i]; s += sS[i]; }
        g_partials[blockIdx.x] = make_float2(c, s);
        __threadfence();                               // publish partial
        unsigned int tk = atomicAdd(&g_ticket, 1u);
        sLast = (tk == (unsigned int)(GRID - 1));
    }
    __syncthreads();

    if (!sLast) return;

    // ---- last block: deterministic fixed-order ALL-FLOAT final reduction ----
    float c = 0.f, s = 0.f;
    #pragma unroll 1
    for (int i = threadIdx.x; i < GRID; i += THREADS) {   // fixed assignment
        float2 p = g_partials[i];
        c += p.x;
        s += p.y;
    }
    #pragma unroll
    for (int o = 16; o; o >>= 1) {
        c += __shfl_xor_sync(0xFFFFFFFFu, c, o);
        s += __shfl_xor_sync(0xFFFFFFFFu, s, o);
    }
    if (lane == 0) { sC[wid] = c; sS[wid] = s; }
    __syncthreads();
    if (threadIdx.x == 0) {
        float tc = 0.f, ts = 0.f;
        #pragma unroll
        for (int i = 0; i < 8; i++) { tc += sC[i]; ts += sS[i]; }
        out[0] = 0.5f * (tc + ts) * INV_NELEM;
        g_ticket = 0u;                                  // reset for next replay
    }
}

extern "C" void kernel_launch(void* const* d_in, const int* in_sizes, int n_in,
                              void* d_out, int out_size) {
    const float* inp = (const float*)d_in[0];
    const float* tgt = (const float*)d_in[1];
    float* out = (float*)d_out;
    jitter_main<<<GRID, THREADS>>>(inp, tgt, out);
}

// round 15
// speedup vs baseline: 1.0208x; 1.0208x over previous
#include <cuda_runtime.h>

// Loss: per element, 9 shifted abs-diffs (3x3 target neighborhood, OOB=0),
// smooth-min via logsumexp(k=32), out = 0.5*(mean(center)+mean(smin)).
//
// R15: revert R14's lg2 poly (latency chain regressed 29.2->34.5; kernel is
// latency-bound, not MUFU-throughput-bound). Attack the real stall source:
// the 6 scalar halo LDGs per float4 (~20 L1 wavefronts, > the 4 vector loads
// combined). Halos now come from neighbor lanes via shfl (lanes 0/31 keep a
// predicated scalar fallback). Also STRIDE % 20 == 0 -> d4 loop-invariant,
// row += STRIDE/20: no integer division in the loop.

constexpr int BATCH = 64;
constexpr int TLEN  = 2048;   // power of 2 -> t via mask
constexpr int DIM   = 80;
constexpr int D4    = DIM / 4;                       // 20 float4 per row
constexpr int N4    = BATCH * TLEN * D4;             // 2,621,440 float4
constexpr float INV_NELEM = 1.0f / (float)((long long)BATCH * TLEN * DIM);

constexpr int THREADS = 256;
constexpr int GRID    = 740;                         // 148 SMs x 5 resident CTAs
constexpr int STRIDE  = GRID * THREADS;              // 189,440
static_assert(STRIDE % D4 == 0, "d4 must be loop-invariant");
constexpr int ROWSTEP = STRIDE / D4;                 // 9,472 rows per stride
// warp-uniform trip counts: split base = N4 - 13*STRIDE = 158,720 = 32*4960
static_assert((N4 - (N4 / STRIDE) * STRIDE) % 32 == 0, "trip split warp-aligned");

__device__ float2 g_partials[GRID];                  // static scratch (no alloc)
__device__ unsigned int g_ticket;                    // zero-init; last block resets

__device__ __forceinline__ float fast_ex2(float x) {
    float y; asm("ex2.approx.ftz.f32 %0, %1;" : "=f"(y) : "f"(x)); return y;
}
__device__ __forceinline__ float fast_lg2(float x) {
    float y; asm("lg2.approx.ftz.f32 %0, %1;" : "=f"(y) : "f"(x)); return y;
}

__global__ __launch_bounds__(THREADS, 5)
void jitter_main(const float* __restrict__ inp, const float* __restrict__ tgt,
                 float* __restrict__ out) {
    const float4* __restrict__ in4  = reinterpret_cast<const float4*>(inp);
    const float4* __restrict__ tg4  = reinterpret_cast<const float4*>(tgt);

    const float KE   = 46.16624131f;   // 32 * log2(e)
    const float IKE  = 0.02166085f;    // ln(2) / 32

    float accC = 0.f, accS = 0.f;

    const int lane = threadIdx.x & 31;

    int i4  = blockIdx.x * THREADS + threadIdx.x;
    int row = i4 / D4;                 // once; afterwards row += ROWSTEP
    const int d4 = i4 - row * D4;      // loop-invariant
    const bool haloL = (d4 > 0);       // dim-left halo exists
    const bool haloR = (d4 < D4 - 1);  // dim-right halo exists

    for (; i4 < N4; i4 += STRIDE, row += ROWSTEP) {
        int t = row & (TLEN - 1);
        bool vm = (t > 0);             // row-1 within same image
        bool vp = (t < TLEN - 1);      // row+1 within same image

        float4 xi = in4[i4];

        // three target rows (vector part); invalid rows read as zero
        float4 cc = tg4[row * D4 + d4];
        float4 cm = make_float4(0.f, 0.f, 0.f, 0.f);
        float4 cp = make_float4(0.f, 0.f, 0.f, 0.f);
        if (vm) cm = tg4[(row - 1) * D4 + d4];
        if (vp) cp = tg4[(row + 1) * D4 + d4];

        // halos from neighbor lanes (lane L-1 holds i4-1 = same row, d4-1).
        // Neighbor's row-validity equals ours when d4>0, and an invalid
        // neighbor row already carries 0 = the pad value.
        float lwc = __shfl_up_sync(0xFFFFFFFFu, cc.w, 1);
        float lwm = __shfl_up_sync(0xFFFFFFFFu, cm.w, 1);
        float lwp = __shfl_up_sync(0xFFFFFFFFu, cp.w, 1);
        float rwc = __shfl_down_sync(0xFFFFFFFFu, cc.x, 1);
        float rwm = __shfl_down_sync(0xFFFFFFFFu, cm.x, 1);
        float rwp = __shfl_down_sync(0xFFFFFFFFu, cp.x, 1);

        float Lc = 0.f, Lm = 0.f, Lp = 0.f, Rc = 0.f, Rm = 0.f, Rp = 0.f;
        if (haloL) {
            if (lane == 0) {           // warp edge: predicated scalar fallback
                Lc = tgt[row * DIM + d4 * 4 - 1];
                if (vm) Lm = tgt[(row - 1) * DIM + d4 * 4 - 1];
                if (vp) Lp = tgt[(row + 1) * DIM + d4 * 4 - 1];
            } else { Lc = lwc; Lm = lwm; Lp = lwp; }
        }
        if (haloR) {
            if (lane == 31) {
                Rc = tgt[row * DIM + d4 * 4 + 4];
                if (vm) Rm = tgt[(row - 1) * DIM + d4 * 4 + 4];
                if (vp) Rp = tgt[(row + 1) * DIM + d4 * 4 + 4];
            } else { Rc = rwc; Rm = rwm; Rp = rwp; }
        }

        // row windows [d-1 .. d+4]
        float nc [6] = {Lc, cc.x, cc.y, cc.z, cc.w, Rc};
        float nm [6] = {Lm, cm.x, cm.y, cm.z, cm.w, Rm};
        float np6[6] = {Lp, cp.x, cp.y, cp.z, cp.w, Rp};

        float xv[4] = {xi.x, xi.y, xi.z, xi.w};

        #pragma unroll
        for (int j = 0; j < 4; j++) {
            float x  = xv[j];
            // 9 shifted abs-diffs: diff(dt,dd) = |x - tgt[t+dt][d+dd]|
            float d0 = fabsf(x - nc [j + 1]);   // ( 0, 0)  center
            float d1 = fabsf(x - np6[j + 1]);   // (+1, 0)
            float d2 = fabsf(x - nm [j + 1]);   // (-1, 0)
            float d3 = fabsf(x - nc [j + 2]);   // ( 0,+1)
            float d4v= fabsf(x - nc [j    ]);   // ( 0,-1)
            float d5 = fabsf(x - np6[j + 2]);   // (+1,+1)
            float d6 = fabsf(x - nm [j    ]);   // (-1,-1)
            float d7 = fabsf(x - np6[j    ]);   // (+1,-1)
            float d8 = fabsf(x - nm [j + 2]);   // (-1,+1)

            float mn = fminf(fminf(fminf(d0, d1), fminf(d2, d3)),
                             fminf(fminf(fminf(d4v, d5), fminf(d6, d7)), d8));

            // logsumexp args: one FFMA each (argmin term ~ulp off 0, harmless)
            float mK = mn * KE;
            float e0 = fast_ex2(fmaf(d0 , -KE, mK));
            float e1 = fast_ex2(fmaf(d1 , -KE, mK));
            float e2 = fast_ex2(fmaf(d2 , -KE, mK));
            float e3 = fast_ex2(fmaf(d3 , -KE, mK));
            float e4 = fast_ex2(fmaf(d4v, -KE, mK));
            float e5 = fast_ex2(fmaf(d5 , -KE, mK));
            float e6 = fast_ex2(fmaf(d6 , -KE, mK));
            float e7 = fast_ex2(fmaf(d7 , -KE, mK));
            float e8 = fast_ex2(fmaf(d8 , -KE, mK));

            // pairwise tree: dep depth 4
            float S = (((e0 + e1) + (e2 + e3)) + ((e4 + e5) + (e6 + e7))) + e8;

            float sm = fmaf(fast_lg2(S), -IKE, mn);

            accC += d0;
            accS += sm;
        }
    }

    // warp reduce
    #pragma unroll
    for (int o = 16; o; o >>= 1) {
        accC += __shfl_xor_sync(0xFFFFFFFFu, accC, o);
        accS += __shfl_xor_sync(0xFFFFFFFFu, accS, o);
    }

    __shared__ float sC[8], sS[8];
    __shared__ bool  sLast;
    int wid = threadIdx.x >> 5;
    if (lane == 0) { sC[wid] = accC; sS[wid] = accS; }
    __syncthreads();

    if (threadIdx.x == 0) {
        float c = 0.f, s = 0.f;
        #pragma unroll
        for (int i = 0; i < 8; i++) { c += sC[i]; s += sS[i]; }
        g_partials[blockIdx.x] = make_float2(c, s);
        __threadfence();                               // publish partial
        unsigned int tk = atomicAdd(&g_ticket, 1u);
        sLast = (tk == (unsigned int)(GRID - 1));
    }
    __syncthreads();

    if (!sLast) return;

    // ---- last block: deterministic fixed-order ALL-FLOAT final reduction ----
    float c = 0.f, s = 0.f;
    #pragma unroll 1
    for (int i = threadIdx.x; i < GRID; i += THREADS) {   // fixed assignment
        float2 p = g_partials[i];
        c += p.x;
        s += p.y;
    }
    #pragma unroll
    for (int o = 16; o; o >>= 1) {
        c += __shfl_xor_sync(0xFFFFFFFFu, c, o);
        s += __shfl_xor_sync(0xFFFFFFFFu, s, o);
    }
    if (lane == 0) { sC[wid] = c; sS[wid] = s; }
    __syncthreads();
    if (threadIdx.x == 0) {
        float tc = 0.f, ts = 0.f;
        #pragma unroll
        for (int i = 0; i < 8; i++) { tc += sC[i]; ts += sS[i]; }
        out[0] = 0.5f * (tc + ts) * INV_NELEM;
        g_ticket = 0u;                                  // reset for next replay
    }
}

extern "C" void kernel_launch(void* const* d_in, const int* in_sizes, int n_in,
                              void* d_out, int out_size) {
    const float* inp = (const float*)d_in[0];
    const float* tgt = (const float*)d_in[1];
    float* out = (float*)d_out;
    jitter_main<<<GRID, THREADS>>>(inp, tgt, out);
}

// round 16
// speedup vs baseline: 1.0977x; 1.0753x over previous
#include <cuda_runtime.h>

// Loss: per element, 9 shifted abs-diffs (3x3 target neighborhood, OOB=0),
// smooth-min via logsumexp(k=32), out = 0.5*(mean(center)+mean(smin)).
//
// R16: R13 body (best: 29.2us) minus instruction fat. Evidence from R14/R15:
// kernel is issue-slot bound (R15 cut L1 40->24% yet slowed; its shfl+selects
// issued ~13% MORE slots than R13's scalar LDGs). So: (a) hoist the i4/D4
// division (STRIDE%20==0 -> d4 invariant, row+=ROWSTEP), (b) all addresses as
// constant offsets from i4 (no row*DIM IMADs), (c) interior fast path: rows
// with t in [1,2046] (99.9%) load 3 rows unconditionally, no vm/vp selects.

constexpr int BATCH = 64;
constexpr int TLEN  = 2048;   // power of 2 -> t via mask
constexpr int DIM   = 80;
constexpr int D4    = DIM / 4;                       // 20 float4 per row
constexpr int N4    = BATCH * TLEN * D4;             // 2,621,440 float4
constexpr float INV_NELEM = 1.0f / (float)((long long)BATCH * TLEN * DIM);

constexpr int THREADS = 256;
constexpr int GRID    = 740;                         // 148 SMs x 5 resident CTAs
constexpr int STRIDE  = GRID * THREADS;              // 189,440
static_assert(STRIDE % D4 == 0, "d4 must be loop-invariant");
constexpr int ROWSTEP = STRIDE / D4;                 // 9,472 rows per stride
static_assert((N4 - (N4 / STRIDE) * STRIDE) % 32 == 0, "trip split warp-aligned");

__device__ float2 g_partials[GRID];                  // static scratch (no alloc)
__device__ unsigned int g_ticket;                    // zero-init; last block resets

__device__ __forceinline__ float fast_ex2(float x) {
    float y; asm("ex2.approx.ftz.f32 %0, %1;" : "=f"(y) : "f"(x)); return y;
}
__device__ __forceinline__ float fast_lg2(float x) {
    float y; asm("lg2.approx.ftz.f32 %0, %1;" : "=f"(y) : "f"(x)); return y;
}

__global__ __launch_bounds__(THREADS, 5)
void jitter_main(const float* __restrict__ inp, const float* __restrict__ tgt,
                 float* __restrict__ out) {
    const float4* __restrict__ in4  = reinterpret_cast<const float4*>(inp);
    const float4* __restrict__ tg4  = reinterpret_cast<const float4*>(tgt);

    const float KE   = 46.16624131f;   // 32 * log2(e)
    const float IKE  = 0.02166085f;    // ln(2) / 32

    float accC = 0.f, accS = 0.f;

    int i4  = blockIdx.x * THREADS + threadIdx.x;
    int row = i4 / D4;                 // once; afterwards row += ROWSTEP
    const int d4 = i4 - row * D4;      // loop-invariant
    const bool haloL = (d4 > 0);
    const bool haloR = (d4 < D4 - 1);

    #pragma unroll 2
    for (; i4 < N4; i4 += STRIDE, row += ROWSTEP) {
        int t = row & (TLEN - 1);

        float4 xi = in4[i4];

        // neighborhood windows [d-1 .. d+4] for rows t-1, t, t+1 (OOB rows = 0)
        float nm[6], nc[6], np6[6];

        // center row: always valid; all addresses are i4 +- constants
        {
            float4 c = tg4[i4];
            nc[1] = c.x; nc[2] = c.y; nc[3] = c.z; nc[4] = c.w;
            nc[0] = haloL ? tgt[4 * i4 - 1] : 0.f;
            nc[5] = haloR ? tgt[4 * i4 + 4] : 0.f;
        }

        if (t > 0 && t < TLEN - 1) {
            // interior fast path (99.9% of rows): both neighbor rows valid,
            // no selects / zero-fills
            float4 a = tg4[i4 - D4];
            nm[1] = a.x; nm[2] = a.y; nm[3] = a.z; nm[4] = a.w;
            nm[0] = haloL ? tgt[4 * i4 - 1 - DIM] : 0.f;
            nm[5] = haloR ? tgt[4 * i4 + 4 - DIM] : 0.f;

            float4 b = tg4[i4 + D4];
            np6[1] = b.x; np6[2] = b.y; np6[3] = b.z; np6[4] = b.w;
            np6[0] = haloL ? tgt[4 * i4 - 1 + DIM] : 0.f;
            np6[5] = haloR ? tgt[4 * i4 + 4 + DIM] : 0.f;
        } else {
            // image edge rows (t==0 or t==TLEN-1)
            if (t > 0) {
                float4 a = tg4[i4 - D4];
                nm[1] = a.x; nm[2] = a.y; nm[3] = a.z; nm[4] = a.w;
                nm[0] = haloL ? tgt[4 * i4 - 1 - DIM] : 0.f;
                nm[5] = haloR ? tgt[4 * i4 + 4 - DIM] : 0.f;
            } else {
                #pragma unroll
                for (int i = 0; i < 6; i++) nm[i] = 0.f;
            }
            if (t < TLEN - 1) {
                float4 b = tg4[i4 + D4];
                np6[1] = b.x; np6[2] = b.y; np6[3] = b.z; np6[4] = b.w;
                np6[0] = haloL ? tgt[4 * i4 - 1 + DIM] : 0.f;
                np6[5] = haloR ? tgt[4 * i4 + 4 + DIM] : 0.f;
            } else {
                #pragma unroll
                for (int i = 0; i < 6; i++) np6[i] = 0.f;
            }
        }

        float xv[4] = {xi.x, xi.y, xi.z, xi.w};

        #pragma unroll
        for (int j = 0; j < 4; j++) {
            float x  = xv[j];
            // 9 shifted abs-diffs: diff(dt,dd) = |x - tgt[t+dt][d+dd]|
            float d0 = fabsf(x - nc [j + 1]);   // ( 0, 0)  center
            float d1 = fabsf(x - np6[j + 1]);   // (+1, 0)
            float d2 = fabsf(x - nm [j + 1]);   // (-1, 0)
            float d3 = fabsf(x - nc [j + 2]);   // ( 0,+1)
            float d4v= fabsf(x - nc [j    ]);   // ( 0,-1)
            float d5 = fabsf(x - np6[j + 2]);   // (+1,+1)
            float d6 = fabsf(x - nm [j    ]);   // (-1,-1)
            float d7 = fabsf(x - np6[j    ]);   // (+1,-1)
            float d8 = fabsf(x - nm [j + 2]);   // (-1,+1)

            float mn = fminf(fminf(fminf(d0, d1), fminf(d2, d3)),
                             fminf(fminf(fminf(d4v, d5), fminf(d6, d7)), d8));

            // logsumexp args: one FFMA each (argmin term ~ulp off 0, harmless)
            float mK = mn * KE;
            float e0 = fast_ex2(fmaf(d0 , -KE, mK));
            float e1 = fast_ex2(fmaf(d1 , -KE, mK));
            float e2 = fast_ex2(fmaf(d2 , -KE, mK));
            float e3 = fast_ex2(fmaf(d3 , -KE, mK));
            float e4 = fast_ex2(fmaf(d4v, -KE, mK));
            float e5 = fast_ex2(fmaf(d5 , -KE, mK));
            float e6 = fast_ex2(fmaf(d6 , -KE, mK));
            float e7 = fast_ex2(fmaf(d7 , -KE, mK));
            float e8 = fast_ex2(fmaf(d8 , -KE, mK));

            // pairwise tree: dep depth 4
            float S = (((e0 + e1) + (e2 + e3)) + ((e4 + e5) + (e6 + e7))) + e8;

            float sm = fmaf(fast_lg2(S), -IKE, mn);

            accC += d0;
            accS += sm;
        }
    }

    // warp reduce
    #pragma unroll
    for (int o = 16; o; o >>= 1) {
        accC += __shfl_xor_sync(0xFFFFFFFFu, accC, o);
        accS += __shfl_xor_sync(0xFFFFFFFFu, accS, o);
    }

    __shared__ float sC[8], sS[8];
    __shared__ bool  sLast;
    int lane = threadIdx.x & 31;
    int wid  = threadIdx.x >> 5;
    if (lane == 0) { sC[wid] = accC; sS[wid] = accS; }
    __syncthreads();

    if (threadIdx.x == 0) {
        float c = 0.f, s = 0.f;
        #pragma unroll
        for (int i = 0; i < 8; i++) { c += sC[i]; s += sS[i]; }
        g_partials[blockIdx.x] = make_float2(c, s);
        __threadfence();                               // publish partial
        unsigned int tk = atomicAdd(&g_ticket, 1u);
        sLast = (tk == (unsigned int)(GRID - 1));
    }
    __syncthreads();

    if (!sLast) return;

    // ---- last block: deterministic fixed-order ALL-FLOAT final reduction ----
    float c = 0.f, s = 0.f;
    #pragma unroll 1
    for (int i = threadIdx.x; i < GRID; i += THREADS) {   // fixed assignment
        float2 p = g_partials[i];
        c += p.x;
        s += p.y;
    }
    #pragma unroll
    for (int o = 16; o; o >>= 1) {
        c += __shfl_xor_sync(0xFFFFFFFFu, c, o);
        s += __shfl_xor_sync(0xFFFFFFFFu, s, o);
    }
    if (lane == 0) { sC[wid] = c; sS[wid] = s; }
    __syncthreads();
    if (threadIdx.x == 0) {
        float tc = 0.f, ts = 0.f;
        #pragma unroll
        for (int i = 0; i < 8; i++) { tc += sC[i]; ts += sS[i]; }
        out[0] = 0.5f * (tc + ts) * INV_NELEM;
        g_ticket = 0u;                                  // reset for next replay
    }
}

extern "C" void kernel_launch(void* const* d_in, const int* in_sizes, int n_in,
                              void* d_out, int out_size) {
    const float* inp = (const float*)d_in[0];
    const float* tgt = (const float*)d_in[1];
    float* out = (float*)d_out;
    jitter_main<<<GRID, THREADS>>>(inp, tgt, out);
}